// round 9
// baseline (speedup 1.0000x reference)
#include <cuda_runtime.h>
#include <math.h>

#define S_LEN 20
#define U_LEN 256
#define NTOK  5120
#define NC    64
#define CANDN 1024
#define HD    128
#define TOPK  10
#define RHO_C 0.02f
#define VGS   24
#define CHUNK 16
#define NWORK_MAX 384

// -------- device scratch --------
__device__ float g_vg[(NC * CANDN + 1) * VGS];
__device__ float g_a[NTOK * VGS];
__device__ int   g_cnt[NC];
__device__ int   g_tok[NC * NTOK];
__device__ int2  g_work[NWORK_MAX + 32];
__device__ int   g_nwork;

// f32x2 helpers
__device__ __forceinline__ unsigned long long f2mul(unsigned long long a, unsigned long long b) {
    unsigned long long d;
    asm("mul.rn.f32x2 %0, %1, %2;" : "=l"(d) : "l"(a), "l"(b));
    return d;
}
__device__ __forceinline__ unsigned long long f2fma(unsigned long long a, unsigned long long b, unsigned long long c) {
    unsigned long long d;
    asm("fma.rn.f32x2 %0, %1, %2, %3;" : "=l"(d) : "l"(a), "l"(b), "l"(c));
    return d;
}
__device__ __forceinline__ unsigned long long f2add(unsigned long long a, unsigned long long b) {
    unsigned long long d;
    asm("add.rn.f32x2 %0, %1, %2;" : "=l"(d) : "l"(a), "l"(b));
    return d;
}

// ============ K_mid (R7, unchanged) ============
__global__ void k_mid(const int* __restrict__ x, const int* __restrict__ tslot,
                      const float* __restrict__ vecs, const int* __restrict__ cand,
                      const int* __restrict__ Iarr, const float* __restrict__ te,
                      const float* __restrict__ Wseq1, const float* __restrict__ bseq1,
                      const float* __restrict__ Wseq2, const float* __restrict__ bseq2,
                      const float* __restrict__ Wto1, const float* __restrict__ bto1,
                      const float* __restrict__ Wto2, const float* __restrict__ bto2,
                      const float* __restrict__ Wti1, const float* __restrict__ bti1,
                      const float* __restrict__ Wti2, const float* __restrict__ bti2) {
    __shared__ float sb[6600];
    int b = blockIdx.x, tid = threadIdx.x;

    if (b < 256) {
        float* W1s = sb;
        float* W2s = sb + 800;
        float* tcs = sb + 1600;
        float* b2s = sb + 1640;
        for (int i = tid; i < 800; i += 128) { W1s[i] = Wti1[i]; W2s[i] = Wti2[i]; }
        if (tid < 40) {
            float acc = bti1[tid];
            #pragma unroll
            for (int i = 0; i < 20; i++) acc += te[40 + i] * Wti1[(20 + i) * 40 + tid];
            tcs[tid] = acc;
        }
        if (tid >= 64 && tid < 84) b2s[tid - 64] = bti2[tid - 64];
        __syncthreads();

        int g0 = b * 256 + tid;
        int v0 = cand[g0], v1 = cand[g0 + 128];
        float in0[20], in1[20];
        const float4* p0 = (const float4*)(vecs + (size_t)v0 * 20);
        const float4* p1 = (const float4*)(vecs + (size_t)v1 * 20);
        #pragma unroll
        for (int q = 0; q < 5; q++) {
            float4 f = p0[q];
            in0[4*q] = f.x; in0[4*q+1] = f.y; in0[4*q+2] = f.z; in0[4*q+3] = f.w;
            float4 h = p1[q];
            in1[4*q] = h.x; in1[4*q+1] = h.y; in1[4*q+2] = h.z; in1[4*q+3] = h.w;
        }
        float o0[20], o1[20];
        #pragma unroll
        for (int d = 0; d < 20; d++) { o0[d] = b2s[d]; o1[d] = b2s[d]; }
        #pragma unroll 2
        for (int a = 0; a < 40; a++) {
            float h0 = tcs[a], h1 = h0;
            #pragma unroll
            for (int i = 0; i < 20; i++) {
                float w = W1s[i * 40 + a];
                h0 += in0[i] * w; h1 += in1[i] * w;
            }
            h0 = fmaxf(h0, 0.0f); h1 = fmaxf(h1, 0.0f);
            #pragma unroll
            for (int d = 0; d < 20; d++) {
                float w = W2s[a * 20 + d];
                o0[d] += h0 * w; o1[d] += h1 * w;
            }
        }
        float n0 = 0.0f, n1 = 0.0f;
        float* d0 = g_vg + (size_t)g0 * VGS;
        float* d1 = g_vg + (size_t)(g0 + 128) * VGS;
        #pragma unroll
        for (int d = 0; d < 20; d++) {
            n0 += o0[d] * o0[d]; d0[d] = o0[d];
            n1 += o1[d] * o1[d]; d1[d] = o1[d];
        }
        d0[20] = n0; d0[21] = 1.0f;
        d1[20] = n1; d1[21] = 1.0f;

    } else if (b < 336) {
        float* Ws1 = sb;
        float* Ws2 = sb + 4000;
        float* Wt1 = sb + 4800;
        float* Wt2 = sb + 5600;
        __shared__ float bs1[40], bs2[20], bt2s[20], tcs2[120];
        for (int i = tid; i < 4000; i += 128) Ws1[i] = Wseq1[i];
        for (int i = tid; i < 800; i += 128) { Ws2[i] = Wseq2[i]; Wt1[i] = Wto1[i]; Wt2[i] = Wto2[i]; }
        if (tid < 40) bs1[tid] = bseq1[tid];
        if (tid >= 64 && tid < 84) { bs2[tid - 64] = bseq2[tid - 64]; bt2s[tid - 64] = bto2[tid - 64]; }
        if (tid < 120) {
            int s = tid / 40, a = tid % 40;
            float acc = bto1[a];
            #pragma unroll
            for (int i = 0; i < 20; i++) acc += te[s * 20 + i] * Wto1[(20 + i) * 40 + a];
            tcs2[tid] = acc;
        }
        __syncthreads();

        int pid = (b - 256) * 128 + tid;
        int n = pid >> 1, h = pid & 1;
        int s = n / U_LEN, u = n % U_LEN;
        int hb = h * 20;

        float hs[20];
        #pragma unroll
        for (int a = 0; a < 20; a++) hs[a] = bs1[hb + a];

        float e[20];
        #pragma unroll 1
        for (int p = 0; p < 5; p++) {
            int k = 4 - p;
            int sel = (s < k) ? s : s - k;
            int xid = x[sel * U_LEN + u];
            const float4* vp = (const float4*)(vecs + (size_t)xid * 20);
            #pragma unroll
            for (int q = 0; q < 5; q++) {
                float4 f = vp[q];
                e[4*q] = f.x; e[4*q+1] = f.y; e[4*q+2] = f.z; e[4*q+3] = f.w;
            }
            #pragma unroll
            for (int i = 0; i < 20; i++) {
                float ei = e[i];
                #pragma unroll
                for (int a = 0; a < 20; a++) hs[a] += ei * Ws1[(p * 20 + i) * 40 + hb + a];
            }
        }

        float po[20];
        #pragma unroll
        for (int d = 0; d < 20; d++) po[d] = 0.0f;
        #pragma unroll 4
        for (int a = 0; a < 20; a++) {
            float r = fmaxf(hs[a], 0.0f);
            #pragma unroll
            for (int d = 0; d < 20; d++) po[d] += r * Ws2[(hb + a) * 20 + d];
        }

        int t24 = tslot[n] % 24;
        int seg = (t24 >= 22 || t24 < 6) ? 0 : (t24 < 14 ? 1 : 2);
        float ht[20];
        #pragma unroll
        for (int a = 0; a < 20; a++) ht[a] = tcs2[seg * 40 + hb + a];
        #pragma unroll
        for (int i = 0; i < 20; i++) {
            float ei = e[i];
            #pragma unroll
            for (int a = 0; a < 20; a++) ht[a] += ei * Wt1[i * 40 + hb + a];
        }
        float px[20];
        #pragma unroll
        for (int d = 0; d < 20; d++) px[d] = 0.0f;
        #pragma unroll 4
        for (int a = 0; a < 20; a++) {
            float r = fmaxf(ht[a], 0.0f);
            #pragma unroll
            for (int d = 0; d < 20; d++) px[d] += r * Wt2[(hb + a) * 20 + d];
        }

        float av[20];
        float nrm = 0.0f;
        #pragma unroll
        for (int d = 0; d < 20; d++) {
            float sp = po[d] + __shfl_xor_sync(0xffffffffu, po[d], 1);
            float tp = px[d] + __shfl_xor_sync(0xffffffffu, px[d], 1);
            av[d] = 0.5f * ((sp + bs2[d]) + (tp + bt2s[d]));
            nrm += av[d] * av[d];
        }
        float* dst = g_a + (size_t)n * VGS;
        #pragma unroll
        for (int d = 0; d < 10; d++) dst[hb / 2 + d] = av[hb / 2 + d];
        if (h == 0) { dst[20] = -0.5f; dst[21] = -0.5f * nrm; }

    } else {
        __shared__ int scnt[NC];
        if (tid < NC) scnt[tid] = 0;
        __syncthreads();
        int xv[40];
        #pragma unroll
        for (int q = 0; q < 40; q++) xv[q] = x[tid + 128 * q];
        int cv[40];
        #pragma unroll
        for (int q = 0; q < 40; q++) cv[q] = Iarr[xv[q]];
        #pragma unroll
        for (int q = 0; q < 40; q++) {
            int c = cv[q];
            int p = atomicAdd(&scnt[c], 1);
            g_tok[c * NTOK + p] = tid + 128 * q;
        }
        __syncthreads();
        if (tid < NC) g_cnt[tid] = scnt[tid];
        if (tid == 0) {
            int w = 0;
            for (int c = 0; c < NC; c++) {
                int cnt = scnt[c];
                for (int st = 0; st < cnt; st += CHUNK) g_work[w++] = make_int2(c, st);
            }
            g_nwork = w;
        }
    }
}

// ============ K3: 512 threads, 16 tokens, 32 cands/lane, warp-parallel merge ============
// smem list layout: row = slice*16 + token (=32*warp+lane at scan time), stride 11 u64,
// slot swizzled by (k + row) % 11 to break merge-phase bank conflicts.
__global__ void __launch_bounds__(512, 2)
k3_score(const int* __restrict__ x, const int* __restrict__ cand,
         const float* __restrict__ Eemb, float* __restrict__ out) {
    int bid = blockIdx.x;
    if (bid >= g_nwork) return;
    int2 wk = g_work[bid];
    int cid = wk.x, start = wk.y;
    int cnt = g_cnt[cid];
    int nIn = min(CHUNK, cnt - start);

    int tid = threadIdx.x, lane = tid & 31, warp = tid >> 5;

    __shared__ unsigned long long part[512 * 11];      // 45KB
    __shared__ float sw_s[CHUNK][12];
    __shared__ int   si_s[CHUNK][12];
    __shared__ int   tok_s[CHUNK];

    if (tid < CHUNK) tok_s[tid] = g_tok[cid * NTOK + start + min(tid, nIn - 1)];
    __syncthreads();

    int tl = lane & 15;
    int half = lane >> 4;
    int slice = warp * 2 + half;           // 0..31
    int token = tok_s[tl];

    const float* ap = g_a + (size_t)token * VGS;
    const ulonglong2* apv = (const ulonglong2*)ap;
    ulonglong2 A0 = apv[0], A1 = apv[1], A2 = apv[2], A3 = apv[3], A4 = apv[4];
    unsigned long long A5 = *(const unsigned long long*)(ap + 20);

    const float* vg = g_vg + (size_t)(cid * CANDN) * VGS;
    int j0 = slice * 32;

    float tv[TOPK]; int tj[TOPK];
    #pragma unroll
    for (int q = 0; q < TOPK; q++) { tv[q] = 3.4e38f; tj[q] = 0; }

    #pragma unroll 2
    for (int jj = 0; jj < 32; jj++) {
        int j = j0 + jj;
        const float* vp = vg + (size_t)j * VGS;
        const ulonglong2* vp2 = (const ulonglong2*)vp;
        ulonglong2 q0 = vp2[0], q1 = vp2[1], q2 = vp2[2], q3 = vp2[3], q4 = vp2[4];
        unsigned long long q5 = *(const unsigned long long*)(vp + 20);
        unsigned long long s0 = f2mul(q0.x, A0.x);
        unsigned long long s1 = f2mul(q0.y, A0.y);
        s0 = f2fma(q1.x, A1.x, s0); s1 = f2fma(q1.y, A1.y, s1);
        s0 = f2fma(q2.x, A2.x, s0); s1 = f2fma(q2.y, A2.y, s1);
        s0 = f2fma(q3.x, A3.x, s0); s1 = f2fma(q3.y, A3.y, s1);
        s0 = f2fma(q4.x, A4.x, s0); s1 = f2fma(q4.y, A4.y, s1);
        s0 = f2fma(q5, A5, s0);
        s0 = f2add(s0, s1);
        float lo = __uint_as_float((unsigned)(s0 & 0xffffffffull));
        float hi = __uint_as_float((unsigned)(s0 >> 32));
        float d2 = fmaxf(-2.0f * (lo + hi), 1e-12f);
        if (d2 < tv[TOPK - 1]) {
            float cv2 = d2; int cj = j;
            #pragma unroll
            for (int q = 0; q < TOPK; q++) {
                bool p = cv2 < tv[q];
                float nv = p ? cv2 : tv[q];
                float xv = p ? tv[q] : cv2;
                int   nj = p ? cj : tj[q];
                int   xj = p ? tj[q] : cj;
                tv[q] = nv; tj[q] = nj; cv2 = xv; cj = xj;
            }
        }
    }

    // store sorted list: row = slice*16 + tl = warp*32 + lane
    {
        int row = slice * 16 + tl;
        int r11 = row % 11;
        #pragma unroll
        for (int q = 0; q < TOPK; q++) {
            int slot = q + r11; if (slot >= 11) slot -= 11;
            part[row * 11 + slot] =
                ((unsigned long long)__float_as_uint(tv[q]) << 32) | (unsigned)tj[q];
        }
    }
    __syncthreads();

    // ---- merge: warp t handles token t; lane = slice ----
    int t = warp;
    if (t < nIn) {
        int row = lane * 16 + t;
        int r11 = row % 11;
        unsigned long long k[TOPK];
        #pragma unroll
        for (int q = 0; q < TOPK; q++) {
            int slot = q + r11; if (slot >= 11) slot -= 11;
            k[q] = part[row * 11 + slot];
        }
        unsigned long long mywin = 0;
        #pragma unroll
        for (int r = 0; r < TOPK; r++) {
            unsigned long long wm = k[0];
            #pragma unroll
            for (int off = 16; off; off >>= 1) {
                unsigned long long o = __shfl_xor_sync(0xffffffffu, wm, off);
                wm = (o < wm) ? o : wm;
            }
            if (lane == r) mywin = wm;
            if (k[0] == wm) {     // unique (j embedded in key)
                #pragma unroll
                for (int q = 0; q < TOPK - 1; q++) k[q] = k[q + 1];
                k[TOPK - 1] = 0xFFFFFFFFFFFFFFFFull;
            }
        }
        // lanes 0..9: winners; lane 10: self
        float e = 0.0f; int ci = 0;
        if (lane < TOPK) {
            float d2 = __uint_as_float((unsigned)(mywin >> 32));
            int j = (int)(mywin & 0xffffffffu);
            float sc = expf(-RHO_C * sqrtf(d2));
            e = expf(sc - 1.0f);
            ci = cand[cid * CANDN + j];
        } else if (lane == TOPK) {
            e = 1.0f;
            ci = x[tok_s[t]];
        }
        float ep = e;
        #pragma unroll
        for (int off = 16; off; off >>= 1) ep += __shfl_xor_sync(0xffffffffu, ep, off);
        float inv = 1.0f / ep;
        if (lane <= TOPK) { sw_s[t][lane] = e * inv; si_s[t][lane] = ci; }
    }
    __syncthreads();

    // ---- weighted embedding gather: warp per token, float4 per lane ----
    if (t < nIn) {
        int token2 = tok_s[t];
        float4 a0 = make_float4(0.f, 0.f, 0.f, 0.f);
        #pragma unroll
        for (int kk = 0; kk < 11; kk++) {
            float w = sw_s[t][kk];
            float4 e0 = ((const float4*)(Eemb + (size_t)si_s[t][kk] * HD))[lane];
            a0.x += w * e0.x; a0.y += w * e0.y; a0.z += w * e0.z; a0.w += w * e0.w;
        }
        ((float4*)(out + (size_t)token2 * HD))[lane] = a0;
    }
}

// ============ launch ============
extern "C" void kernel_launch(void* const* d_in, const int* in_sizes, int n_in,
                              void* d_out, int out_size) {
    const int*   x     = (const int*)  d_in[0];
    const int*   tslot = (const int*)  d_in[1];
    const float* vecs  = (const float*)d_in[2];
    const float* Eemb  = (const float*)d_in[3];
    const int*   Iarr  = (const int*)  d_in[4];
    const int*   cand  = (const int*)  d_in[5];
    const float* te    = (const float*)d_in[6];
    const float* Wseq1 = (const float*)d_in[7];
    const float* bseq1 = (const float*)d_in[8];
    const float* Wseq2 = (const float*)d_in[9];
    const float* bseq2 = (const float*)d_in[10];
    const float* Wto1  = (const float*)d_in[11];
    const float* bto1  = (const float*)d_in[12];
    const float* Wto2  = (const float*)d_in[13];
    const float* bto2  = (const float*)d_in[14];
    const float* Wti1  = (const float*)d_in[15];
    const float* bti1  = (const float*)d_in[16];
    const float* Wti2  = (const float*)d_in[17];
    const float* bti2  = (const float*)d_in[18];
    float* out = (float*)d_out;

    k_mid<<<337, 128>>>(x, tslot, vecs, cand, Iarr, te,
                        Wseq1, bseq1, Wseq2, bseq2,
                        Wto1, bto1, Wto2, bto2,
                        Wti1, bti1, Wti2, bti2);
    k3_score<<<NWORK_MAX, 512>>>(x, cand, Eemb, out);
}

// round 10
// speedup vs baseline: 1.0550x; 1.0550x over previous
#include <cuda_runtime.h>
#include <math.h>

#define S_LEN 20
#define U_LEN 256
#define NTOK  5120
#define NC    64
#define CANDN 1024
#define HD    128
#define TOPK  10
#define RHO_C 0.02f
#define VGS   24
#define CHUNK 16
#define NWORK_MAX 384
#define D2STR 1025           // d2 row stride (odd -> conflict-free)
#define SCAP  96             // survivor list capacity
#define K3_SMEM 80000

// -------- device scratch --------
__device__ float g_vg[(NC * CANDN + 1) * VGS];
__device__ float g_a[NTOK * VGS];
__device__ int   g_cnt[NC];
__device__ int   g_tok[NC * NTOK];
__device__ int2  g_work[NWORK_MAX + 32];
__device__ int   g_nwork;

// f32x2 helpers
__device__ __forceinline__ unsigned long long f2mul(unsigned long long a, unsigned long long b) {
    unsigned long long d;
    asm("mul.rn.f32x2 %0, %1, %2;" : "=l"(d) : "l"(a), "l"(b));
    return d;
}
__device__ __forceinline__ unsigned long long f2fma(unsigned long long a, unsigned long long b, unsigned long long c) {
    unsigned long long d;
    asm("fma.rn.f32x2 %0, %1, %2, %3;" : "=l"(d) : "l"(a), "l"(b), "l"(c));
    return d;
}
__device__ __forceinline__ unsigned long long f2add(unsigned long long a, unsigned long long b) {
    unsigned long long d;
    asm("add.rn.f32x2 %0, %1, %2;" : "=l"(d) : "l"(a), "l"(b));
    return d;
}

// ============ K_mid (unchanged — best known) ============
__global__ void k_mid(const int* __restrict__ x, const int* __restrict__ tslot,
                      const float* __restrict__ vecs, const int* __restrict__ cand,
                      const int* __restrict__ Iarr, const float* __restrict__ te,
                      const float* __restrict__ Wseq1, const float* __restrict__ bseq1,
                      const float* __restrict__ Wseq2, const float* __restrict__ bseq2,
                      const float* __restrict__ Wto1, const float* __restrict__ bto1,
                      const float* __restrict__ Wto2, const float* __restrict__ bto2,
                      const float* __restrict__ Wti1, const float* __restrict__ bti1,
                      const float* __restrict__ Wti2, const float* __restrict__ bti2) {
    __shared__ float sb[6600];
    int b = blockIdx.x, tid = threadIdx.x;

    if (b < 256) {
        float* W1s = sb;
        float* W2s = sb + 800;
        float* tcs = sb + 1600;
        float* b2s = sb + 1640;
        for (int i = tid; i < 800; i += 128) { W1s[i] = Wti1[i]; W2s[i] = Wti2[i]; }
        if (tid < 40) {
            float acc = bti1[tid];
            #pragma unroll
            for (int i = 0; i < 20; i++) acc += te[40 + i] * Wti1[(20 + i) * 40 + tid];
            tcs[tid] = acc;
        }
        if (tid >= 64 && tid < 84) b2s[tid - 64] = bti2[tid - 64];
        __syncthreads();

        int g0 = b * 256 + tid;
        int v0 = cand[g0], v1 = cand[g0 + 128];
        float in0[20], in1[20];
        const float4* p0 = (const float4*)(vecs + (size_t)v0 * 20);
        const float4* p1 = (const float4*)(vecs + (size_t)v1 * 20);
        #pragma unroll
        for (int q = 0; q < 5; q++) {
            float4 f = p0[q];
            in0[4*q] = f.x; in0[4*q+1] = f.y; in0[4*q+2] = f.z; in0[4*q+3] = f.w;
            float4 h = p1[q];
            in1[4*q] = h.x; in1[4*q+1] = h.y; in1[4*q+2] = h.z; in1[4*q+3] = h.w;
        }
        float o0[20], o1[20];
        #pragma unroll
        for (int d = 0; d < 20; d++) { o0[d] = b2s[d]; o1[d] = b2s[d]; }
        #pragma unroll 2
        for (int a = 0; a < 40; a++) {
            float h0 = tcs[a], h1 = h0;
            #pragma unroll
            for (int i = 0; i < 20; i++) {
                float w = W1s[i * 40 + a];
                h0 += in0[i] * w; h1 += in1[i] * w;
            }
            h0 = fmaxf(h0, 0.0f); h1 = fmaxf(h1, 0.0f);
            #pragma unroll
            for (int d = 0; d < 20; d++) {
                float w = W2s[a * 20 + d];
                o0[d] += h0 * w; o1[d] += h1 * w;
            }
        }
        float n0 = 0.0f, n1 = 0.0f;
        float* d0 = g_vg + (size_t)g0 * VGS;
        float* d1 = g_vg + (size_t)(g0 + 128) * VGS;
        #pragma unroll
        for (int d = 0; d < 20; d++) {
            n0 += o0[d] * o0[d]; d0[d] = o0[d];
            n1 += o1[d] * o1[d]; d1[d] = o1[d];
        }
        d0[20] = n0; d0[21] = 1.0f;
        d1[20] = n1; d1[21] = 1.0f;

    } else if (b < 336) {
        float* Ws1 = sb;
        float* Ws2 = sb + 4000;
        float* Wt1 = sb + 4800;
        float* Wt2 = sb + 5600;
        __shared__ float bs1[40], bs2[20], bt2s[20], tcs2[120];
        for (int i = tid; i < 4000; i += 128) Ws1[i] = Wseq1[i];
        for (int i = tid; i < 800; i += 128) { Ws2[i] = Wseq2[i]; Wt1[i] = Wto1[i]; Wt2[i] = Wto2[i]; }
        if (tid < 40) bs1[tid] = bseq1[tid];
        if (tid >= 64 && tid < 84) { bs2[tid - 64] = bseq2[tid - 64]; bt2s[tid - 64] = bto2[tid - 64]; }
        if (tid < 120) {
            int s = tid / 40, a = tid % 40;
            float acc = bto1[a];
            #pragma unroll
            for (int i = 0; i < 20; i++) acc += te[s * 20 + i] * Wto1[(20 + i) * 40 + a];
            tcs2[tid] = acc;
        }
        __syncthreads();

        int pid = (b - 256) * 128 + tid;
        int n = pid >> 1, h = pid & 1;
        int s = n / U_LEN, u = n % U_LEN;
        int hb = h * 20;

        float hs[20];
        #pragma unroll
        for (int a = 0; a < 20; a++) hs[a] = bs1[hb + a];

        float e[20];
        #pragma unroll 1
        for (int p = 0; p < 5; p++) {
            int k = 4 - p;
            int sel = (s < k) ? s : s - k;
            int xid = x[sel * U_LEN + u];
            const float4* vp = (const float4*)(vecs + (size_t)xid * 20);
            #pragma unroll
            for (int q = 0; q < 5; q++) {
                float4 f = vp[q];
                e[4*q] = f.x; e[4*q+1] = f.y; e[4*q+2] = f.z; e[4*q+3] = f.w;
            }
            #pragma unroll
            for (int i = 0; i < 20; i++) {
                float ei = e[i];
                #pragma unroll
                for (int a = 0; a < 20; a++) hs[a] += ei * Ws1[(p * 20 + i) * 40 + hb + a];
            }
        }

        float po[20];
        #pragma unroll
        for (int d = 0; d < 20; d++) po[d] = 0.0f;
        #pragma unroll 4
        for (int a = 0; a < 20; a++) {
            float r = fmaxf(hs[a], 0.0f);
            #pragma unroll
            for (int d = 0; d < 20; d++) po[d] += r * Ws2[(hb + a) * 20 + d];
        }

        int t24 = tslot[n] % 24;
        int seg = (t24 >= 22 || t24 < 6) ? 0 : (t24 < 14 ? 1 : 2);
        float ht[20];
        #pragma unroll
        for (int a = 0; a < 20; a++) ht[a] = tcs2[seg * 40 + hb + a];
        #pragma unroll
        for (int i = 0; i < 20; i++) {
            float ei = e[i];
            #pragma unroll
            for (int a = 0; a < 20; a++) ht[a] += ei * Wt1[i * 40 + hb + a];
        }
        float px[20];
        #pragma unroll
        for (int d = 0; d < 20; d++) px[d] = 0.0f;
        #pragma unroll 4
        for (int a = 0; a < 20; a++) {
            float r = fmaxf(ht[a], 0.0f);
            #pragma unroll
            for (int d = 0; d < 20; d++) px[d] += r * Wt2[(hb + a) * 20 + d];
        }

        float av[20];
        float nrm = 0.0f;
        #pragma unroll
        for (int d = 0; d < 20; d++) {
            float sp = po[d] + __shfl_xor_sync(0xffffffffu, po[d], 1);
            float tp = px[d] + __shfl_xor_sync(0xffffffffu, px[d], 1);
            av[d] = 0.5f * ((sp + bs2[d]) + (tp + bt2s[d]));
            nrm += av[d] * av[d];
        }
        float* dst = g_a + (size_t)n * VGS;
        #pragma unroll
        for (int d = 0; d < 10; d++) dst[hb / 2 + d] = av[hb / 2 + d];
        if (h == 0) { dst[20] = -0.5f; dst[21] = -0.5f * nrm; }

    } else {
        __shared__ int scnt[NC];
        if (tid < NC) scnt[tid] = 0;
        __syncthreads();
        int xv[40];
        #pragma unroll
        for (int q = 0; q < 40; q++) xv[q] = x[tid + 128 * q];
        int cv[40];
        #pragma unroll
        for (int q = 0; q < 40; q++) cv[q] = Iarr[xv[q]];
        #pragma unroll
        for (int q = 0; q < 40; q++) {
            int c = cv[q];
            int p = atomicAdd(&scnt[c], 1);
            g_tok[c * NTOK + p] = tid + 128 * q;
        }
        __syncthreads();
        if (tid < NC) g_cnt[tid] = scnt[tid];
        if (tid == 0) {
            int w = 0;
            for (int c = 0; c < NC; c++) {
                int cnt = scnt[c];
                for (int st = 0; st < cnt; st += CHUNK) g_work[w++] = make_int2(c, st);
            }
            g_nwork = w;
        }
    }
}

// ============ K3 v2: phase-split d2 matrix + threshold selection ============
// 512 threads, 16 tokens. Phase 1: warp w computes rows [w*64,w*64+64),
// lane=(half,token) -> 2 rows/step, d2 -> smem matrix. Phase 2: warp w = token w.
__global__ void __launch_bounds__(512, 2)
k3_score(const int* __restrict__ x, const int* __restrict__ cand,
         const float* __restrict__ Eemb, float* __restrict__ out) {
    extern __shared__ char smraw[];
    float* d2mat = (float*)smraw;                               // 16*1025*4 = 65600
    float* lv    = (float*)(smraw + 65600);                     // 16*96*4 = 6144
    int*   lj    = (int*)  (smraw + 71744);                     // 6144
    float* sw_s  = (float*)(smraw + 77888);                     // 16*12*4 = 768
    int*   si_s  = (int*)  (smraw + 78656);                     // 768
    int*   tok_s = (int*)  (smraw + 79424);                     // 64
    int*   lcnt  = (int*)  (smraw + 79488);                     // 64

    int bid = blockIdx.x;
    if (bid >= g_nwork) return;
    int2 wk = g_work[bid];
    int cid = wk.x, start = wk.y;
    int cnt = g_cnt[cid];
    int nIn = min(CHUNK, cnt - start);

    int tid = threadIdx.x, lane = tid & 31, warp = tid >> 5;

    if (tid < CHUNK) {
        tok_s[tid] = g_tok[cid * NTOK + start + min(tid, nIn - 1)];
        lcnt[tid] = 0;
    }
    __syncthreads();

    // ---------------- phase 1: d2 matrix ----------------
    {
        int tl = lane & 15;
        int half = lane >> 4;
        int token = tok_s[tl];

        const float* ap = g_a + (size_t)token * VGS;
        const ulonglong2* apv = (const ulonglong2*)ap;
        ulonglong2 A0 = apv[0], A1 = apv[1], A2 = apv[2], A3 = apv[3], A4 = apv[4];
        unsigned long long A5 = *(const unsigned long long*)(ap + 20);

        const float* vg = g_vg + (size_t)(cid * CANDN) * VGS;
        int jbase = warp * 64 + half;

        #pragma unroll 2
        for (int s = 0; s < 32; s++) {
            int j = jbase + 2 * s;
            const float* vp = vg + (size_t)j * VGS;
            const ulonglong2* vp2 = (const ulonglong2*)vp;
            ulonglong2 q0 = vp2[0], q1 = vp2[1], q2 = vp2[2], q3 = vp2[3], q4 = vp2[4];
            unsigned long long q5 = *(const unsigned long long*)(vp + 20);
            unsigned long long s0 = f2mul(q0.x, A0.x);
            unsigned long long s1 = f2mul(q0.y, A0.y);
            s0 = f2fma(q1.x, A1.x, s0); s1 = f2fma(q1.y, A1.y, s1);
            s0 = f2fma(q2.x, A2.x, s0); s1 = f2fma(q2.y, A2.y, s1);
            s0 = f2fma(q3.x, A3.x, s0); s1 = f2fma(q3.y, A3.y, s1);
            s0 = f2fma(q4.x, A4.x, s0); s1 = f2fma(q4.y, A4.y, s1);
            s0 = f2fma(q5, A5, s0);
            s0 = f2add(s0, s1);
            float lo = __uint_as_float((unsigned)(s0 & 0xffffffffull));
            float hi = __uint_as_float((unsigned)(s0 >> 32));
            float d2 = fmaxf(-2.0f * (lo + hi), 1e-12f);
            d2mat[tl * D2STR + j] = d2;
        }
    }
    __syncthreads();

    // ---------------- phase 2: per-token selection (warp = token) ----------------
    int t = warp;     // 0..15
    {
        // cache my 32 values, find lane min
        float vc[32];
        float mv = 3.4e38f;
        #pragma unroll
        for (int i = 0; i < 32; i++) {
            float v = d2mat[t * D2STR + i * 32 + lane];
            vc[i] = v;
            mv = fminf(mv, v);
        }
        // tau = 10th smallest lane-min (safe, tight threshold)
        float cur = mv, tau = 3.4e38f;
        #pragma unroll
        for (int r = 0; r < TOPK; r++) {
            float m = cur;
            #pragma unroll
            for (int off = 16; off; off >>= 1)
                m = fminf(m, __shfl_xor_sync(0xffffffffu, m, off));
            tau = m;
            if (cur == m) cur = 3.4e38f;
        }
        // filtered append
        #pragma unroll
        for (int i = 0; i < 32; i++) {
            if (vc[i] <= tau) {
                int p = atomicAdd(&lcnt[t], 1);
                if (p < SCAP) {
                    lv[t * SCAP + p] = vc[i];
                    lj[t * SCAP + p] = i * 32 + lane;
                }
            }
        }
        __syncwarp();

        // exact top-10 over survivors
        int n = min(lcnt[t], SCAP);
        float v3[3];
        #pragma unroll
        for (int q = 0; q < 3; q++) {
            int g = lane + 32 * q;
            v3[q] = (g < n) ? lv[t * SCAP + g] : 3.4e38f;
        }
        float rv = 0.0f; int rg = 0;
        #pragma unroll
        for (int r = 0; r < TOPK; r++) {
            float bv = v3[0]; int bq = 0;
            if (v3[1] < bv) { bv = v3[1]; bq = 1; }
            if (v3[2] < bv) { bv = v3[2]; bq = 2; }
            int bg = lane + 32 * bq;
            float wv = bv; int wg = bg;
            #pragma unroll
            for (int off = 16; off; off >>= 1) {
                float ov = __shfl_xor_sync(0xffffffffu, wv, off);
                int   og = __shfl_xor_sync(0xffffffffu, wg, off);
                if (ov < wv || (ov == wv && og < wg)) { wv = ov; wg = og; }
            }
            if ((wg & 31) == lane) {
                int q = wg >> 5;
                if (q == 0) v3[0] = 3.4e38f;
                else if (q == 1) v3[1] = 3.4e38f;
                else v3[2] = 3.4e38f;
            }
            if (lane == r) { rv = wv; rg = wg; }
        }

        // weights + ids (lanes 0..9 winners, lane 10 self)
        float e = 0.0f; int ci = 0;
        if (lane < TOPK) {
            float sc = expf(-RHO_C * sqrtf(rv));
            e = expf(sc - 1.0f);
            ci = cand[cid * CANDN + lj[t * SCAP + rg]];
        } else if (lane == TOPK) {
            e = 1.0f;
            ci = x[tok_s[t]];
        }
        float ep = e;
        #pragma unroll
        for (int off = 16; off; off >>= 1) ep += __shfl_xor_sync(0xffffffffu, ep, off);
        float inv = 1.0f / ep;
        if (lane <= TOPK) { sw_s[t * 12 + lane] = e * inv; si_s[t * 12 + lane] = ci; }
    }
    __syncwarp();

    // ---------------- epilogue: weighted embedding gather ----------------
    if (t < nIn) {
        int token2 = tok_s[t];
        float4 a0 = make_float4(0.f, 0.f, 0.f, 0.f);
        #pragma unroll
        for (int kk = 0; kk < 11; kk++) {
            float w = sw_s[t * 12 + kk];
            float4 e0 = ((const float4*)(Eemb + (size_t)si_s[t * 12 + kk] * HD))[lane];
            a0.x += w * e0.x; a0.y += w * e0.y; a0.z += w * e0.z; a0.w += w * e0.w;
        }
        ((float4*)(out + (size_t)token2 * HD))[lane] = a0;
    }
}

// ============ launch ============
extern "C" void kernel_launch(void* const* d_in, const int* in_sizes, int n_in,
                              void* d_out, int out_size) {
    const int*   x     = (const int*)  d_in[0];
    const int*   tslot = (const int*)  d_in[1];
    const float* vecs  = (const float*)d_in[2];
    const float* Eemb  = (const float*)d_in[3];
    const int*   Iarr  = (const int*)  d_in[4];
    const int*   cand  = (const int*)  d_in[5];
    const float* te    = (const float*)d_in[6];
    const float* Wseq1 = (const float*)d_in[7];
    const float* bseq1 = (const float*)d_in[8];
    const float* Wseq2 = (const float*)d_in[9];
    const float* bseq2 = (const float*)d_in[10];
    const float* Wto1  = (const float*)d_in[11];
    const float* bto1  = (const float*)d_in[12];
    const float* Wto2  = (const float*)d_in[13];
    const float* bto2  = (const float*)d_in[14];
    const float* Wti1  = (const float*)d_in[15];
    const float* bti1  = (const float*)d_in[16];
    const float* Wti2  = (const float*)d_in[17];
    const float* bti2  = (const float*)d_in[18];
    float* out = (float*)d_out;

    cudaFuncSetAttribute(k3_score, cudaFuncAttributeMaxDynamicSharedMemorySize, K3_SMEM);

    k_mid<<<337, 128>>>(x, tslot, vecs, cand, Iarr, te,
                        Wseq1, bseq1, Wseq2, bseq2,
                        Wto1, bto1, Wto2, bto2,
                        Wti1, bti1, Wti2, bti2);
    k3_score<<<NWORK_MAX, 512, K3_SMEM>>>(x, cand, Eemb, out);
}

// round 11
// speedup vs baseline: 1.2320x; 1.1678x over previous
#include <cuda_runtime.h>
#include <math.h>

#define S_LEN 20
#define U_LEN 256
#define NTOK  5120
#define NC    64
#define CANDN 1024
#define HD    128
#define TOPK  10
#define RHO_C 0.02f
#define VGS   24
#define CHUNK 16
#define NWORK_MAX 384
#define D2STR 1025           // d2 row stride (odd -> conflict-free)
#define SCAP  64             // survivor list capacity
// smem layout (bytes)
#define OFF_LV   65600
#define OFF_LJ   69696
#define OFF_SW   73792
#define OFF_SI   74560
#define OFF_TOK  75328
#define OFF_LCNT 75392
#define K3_SMEM  75456

// -------- device scratch (g_vg padded +1 row: prefetch overrun target) --------
__device__ float g_vg[(NC * CANDN + 1) * VGS];
__device__ float g_a[NTOK * VGS];
__device__ int   g_cnt[NC];
__device__ int   g_tok[NC * NTOK];
__device__ int2  g_work[NWORK_MAX + 32];
__device__ int   g_nwork;

// f32x2 helpers
__device__ __forceinline__ unsigned long long f2mul(unsigned long long a, unsigned long long b) {
    unsigned long long d;
    asm("mul.rn.f32x2 %0, %1, %2;" : "=l"(d) : "l"(a), "l"(b));
    return d;
}
__device__ __forceinline__ unsigned long long f2fma(unsigned long long a, unsigned long long b, unsigned long long c) {
    unsigned long long d;
    asm("fma.rn.f32x2 %0, %1, %2, %3;" : "=l"(d) : "l"(a), "l"(b), "l"(c));
    return d;
}
__device__ __forceinline__ unsigned long long f2add(unsigned long long a, unsigned long long b) {
    unsigned long long d;
    asm("add.rn.f32x2 %0, %1, %2;" : "=l"(d) : "l"(a), "l"(b));
    return d;
}

// ============ K_mid (unchanged — best known) ============
__global__ void k_mid(const int* __restrict__ x, const int* __restrict__ tslot,
                      const float* __restrict__ vecs, const int* __restrict__ cand,
                      const int* __restrict__ Iarr, const float* __restrict__ te,
                      const float* __restrict__ Wseq1, const float* __restrict__ bseq1,
                      const float* __restrict__ Wseq2, const float* __restrict__ bseq2,
                      const float* __restrict__ Wto1, const float* __restrict__ bto1,
                      const float* __restrict__ Wto2, const float* __restrict__ bto2,
                      const float* __restrict__ Wti1, const float* __restrict__ bti1,
                      const float* __restrict__ Wti2, const float* __restrict__ bti2) {
    __shared__ float sb[6600];
    int b = blockIdx.x, tid = threadIdx.x;

    if (b < 256) {
        float* W1s = sb;
        float* W2s = sb + 800;
        float* tcs = sb + 1600;
        float* b2s = sb + 1640;
        for (int i = tid; i < 800; i += 128) { W1s[i] = Wti1[i]; W2s[i] = Wti2[i]; }
        if (tid < 40) {
            float acc = bti1[tid];
            #pragma unroll
            for (int i = 0; i < 20; i++) acc += te[40 + i] * Wti1[(20 + i) * 40 + tid];
            tcs[tid] = acc;
        }
        if (tid >= 64 && tid < 84) b2s[tid - 64] = bti2[tid - 64];
        __syncthreads();

        int g0 = b * 256 + tid;
        int v0 = cand[g0], v1 = cand[g0 + 128];
        float in0[20], in1[20];
        const float4* p0 = (const float4*)(vecs + (size_t)v0 * 20);
        const float4* p1 = (const float4*)(vecs + (size_t)v1 * 20);
        #pragma unroll
        for (int q = 0; q < 5; q++) {
            float4 f = p0[q];
            in0[4*q] = f.x; in0[4*q+1] = f.y; in0[4*q+2] = f.z; in0[4*q+3] = f.w;
            float4 h = p1[q];
            in1[4*q] = h.x; in1[4*q+1] = h.y; in1[4*q+2] = h.z; in1[4*q+3] = h.w;
        }
        float o0[20], o1[20];
        #pragma unroll
        for (int d = 0; d < 20; d++) { o0[d] = b2s[d]; o1[d] = b2s[d]; }
        #pragma unroll 2
        for (int a = 0; a < 40; a++) {
            float h0 = tcs[a], h1 = h0;
            #pragma unroll
            for (int i = 0; i < 20; i++) {
                float w = W1s[i * 40 + a];
                h0 += in0[i] * w; h1 += in1[i] * w;
            }
            h0 = fmaxf(h0, 0.0f); h1 = fmaxf(h1, 0.0f);
            #pragma unroll
            for (int d = 0; d < 20; d++) {
                float w = W2s[a * 20 + d];
                o0[d] += h0 * w; o1[d] += h1 * w;
            }
        }
        float n0 = 0.0f, n1 = 0.0f;
        float* d0 = g_vg + (size_t)g0 * VGS;
        float* d1 = g_vg + (size_t)(g0 + 128) * VGS;
        #pragma unroll
        for (int d = 0; d < 20; d++) {
            n0 += o0[d] * o0[d]; d0[d] = o0[d];
            n1 += o1[d] * o1[d]; d1[d] = o1[d];
        }
        d0[20] = n0; d0[21] = 1.0f;
        d1[20] = n1; d1[21] = 1.0f;

    } else if (b < 336) {
        float* Ws1 = sb;
        float* Ws2 = sb + 4000;
        float* Wt1 = sb + 4800;
        float* Wt2 = sb + 5600;
        __shared__ float bs1[40], bs2[20], bt2s[20], tcs2[120];
        for (int i = tid; i < 4000; i += 128) Ws1[i] = Wseq1[i];
        for (int i = tid; i < 800; i += 128) { Ws2[i] = Wseq2[i]; Wt1[i] = Wto1[i]; Wt2[i] = Wto2[i]; }
        if (tid < 40) bs1[tid] = bseq1[tid];
        if (tid >= 64 && tid < 84) { bs2[tid - 64] = bseq2[tid - 64]; bt2s[tid - 64] = bto2[tid - 64]; }
        if (tid < 120) {
            int s = tid / 40, a = tid % 40;
            float acc = bto1[a];
            #pragma unroll
            for (int i = 0; i < 20; i++) acc += te[s * 20 + i] * Wto1[(20 + i) * 40 + a];
            tcs2[tid] = acc;
        }
        __syncthreads();

        int pid = (b - 256) * 128 + tid;
        int n = pid >> 1, h = pid & 1;
        int s = n / U_LEN, u = n % U_LEN;
        int hb = h * 20;

        float hs[20];
        #pragma unroll
        for (int a = 0; a < 20; a++) hs[a] = bs1[hb + a];

        float e[20];
        #pragma unroll 1
        for (int p = 0; p < 5; p++) {
            int k = 4 - p;
            int sel = (s < k) ? s : s - k;
            int xid = x[sel * U_LEN + u];
            const float4* vp = (const float4*)(vecs + (size_t)xid * 20);
            #pragma unroll
            for (int q = 0; q < 5; q++) {
                float4 f = vp[q];
                e[4*q] = f.x; e[4*q+1] = f.y; e[4*q+2] = f.z; e[4*q+3] = f.w;
            }
            #pragma unroll
            for (int i = 0; i < 20; i++) {
                float ei = e[i];
                #pragma unroll
                for (int a = 0; a < 20; a++) hs[a] += ei * Ws1[(p * 20 + i) * 40 + hb + a];
            }
        }

        float po[20];
        #pragma unroll
        for (int d = 0; d < 20; d++) po[d] = 0.0f;
        #pragma unroll 4
        for (int a = 0; a < 20; a++) {
            float r = fmaxf(hs[a], 0.0f);
            #pragma unroll
            for (int d = 0; d < 20; d++) po[d] += r * Ws2[(hb + a) * 20 + d];
        }

        int t24 = tslot[n] % 24;
        int seg = (t24 >= 22 || t24 < 6) ? 0 : (t24 < 14 ? 1 : 2);
        float ht[20];
        #pragma unroll
        for (int a = 0; a < 20; a++) ht[a] = tcs2[seg * 40 + hb + a];
        #pragma unroll
        for (int i = 0; i < 20; i++) {
            float ei = e[i];
            #pragma unroll
            for (int a = 0; a < 20; a++) ht[a] += ei * Wt1[i * 40 + hb + a];
        }
        float px[20];
        #pragma unroll
        for (int d = 0; d < 20; d++) px[d] = 0.0f;
        #pragma unroll 4
        for (int a = 0; a < 20; a++) {
            float r = fmaxf(ht[a], 0.0f);
            #pragma unroll
            for (int d = 0; d < 20; d++) px[d] += r * Wt2[(hb + a) * 20 + d];
        }

        float av[20];
        float nrm = 0.0f;
        #pragma unroll
        for (int d = 0; d < 20; d++) {
            float sp = po[d] + __shfl_xor_sync(0xffffffffu, po[d], 1);
            float tp = px[d] + __shfl_xor_sync(0xffffffffu, px[d], 1);
            av[d] = 0.5f * ((sp + bs2[d]) + (tp + bt2s[d]));
            nrm += av[d] * av[d];
        }
        float* dst = g_a + (size_t)n * VGS;
        #pragma unroll
        for (int d = 0; d < 10; d++) dst[hb / 2 + d] = av[hb / 2 + d];
        if (h == 0) { dst[20] = -0.5f; dst[21] = -0.5f * nrm; }

    } else {
        __shared__ int scnt[NC];
        if (tid < NC) scnt[tid] = 0;
        __syncthreads();
        int xv[40];
        #pragma unroll
        for (int q = 0; q < 40; q++) xv[q] = x[tid + 128 * q];
        int cv[40];
        #pragma unroll
        for (int q = 0; q < 40; q++) cv[q] = Iarr[xv[q]];
        #pragma unroll
        for (int q = 0; q < 40; q++) {
            int c = cv[q];
            int p = atomicAdd(&scnt[c], 1);
            g_tok[c * NTOK + p] = tid + 128 * q;
        }
        __syncthreads();
        if (tid < NC) g_cnt[tid] = scnt[tid];
        if (tid == 0) {
            int w = 0;
            for (int c = 0; c < NC; c++) {
                int cnt = scnt[c];
                for (int st = 0; st < cnt; st += CHUNK) g_work[w++] = make_int2(c, st);
            }
            g_nwork = w;
        }
    }
}

// ============ K3 v3: prefetched d2 matrix (phase 1) + tau-filtered exact top-10 (phase 2)
// 256 threads, occ 3. Phase 1: R7's double-buffered loop, body = STS only.
__global__ void __launch_bounds__(256, 3)
k3_score(const int* __restrict__ x, const int* __restrict__ cand,
         const float* __restrict__ Eemb, float* __restrict__ out) {
    extern __shared__ char smraw[];
    float* d2mat = (float*)smraw;
    float* lv    = (float*)(smraw + OFF_LV);
    int*   lj    = (int*)  (smraw + OFF_LJ);
    float* sw_s  = (float*)(smraw + OFF_SW);
    int*   si_s  = (int*)  (smraw + OFF_SI);
    int*   tok_s = (int*)  (smraw + OFF_TOK);
    int*   lcnt  = (int*)  (smraw + OFF_LCNT);

    int bid = blockIdx.x;
    if (bid >= g_nwork) return;
    int2 wk = g_work[bid];
    int cid = wk.x, start = wk.y;
    int cnt = g_cnt[cid];
    int nIn = min(CHUNK, cnt - start);

    int tid = threadIdx.x, lane = tid & 31, warp = tid >> 5;

    if (tid < CHUNK) {
        tok_s[tid] = g_tok[cid * NTOK + start + min(tid, nIn - 1)];
        lcnt[tid] = 0;
    }
    __syncthreads();

    // ---------------- phase 1: d2 matrix with double-buffered prefetch ----------------
    {
        int tl = lane & 15;
        int half = lane >> 4;
        int token = tok_s[tl];

        const float* ap = g_a + (size_t)token * VGS;
        const ulonglong2* apv = (const ulonglong2*)ap;
        ulonglong2 A0 = apv[0], A1 = apv[1], A2 = apv[2], A3 = apv[3], A4 = apv[4];
        unsigned long long A5 = *(const unsigned long long*)(ap + 20);

        const float* vg = g_vg + (size_t)(cid * CANDN) * VGS;
        int j0 = warp * 128 + half * 64;
        float* drow = d2mat + tl * D2STR + j0;

        const float* vp = vg + (size_t)j0 * VGS;
        ulonglong2 q0 = ((const ulonglong2*)vp)[0];
        ulonglong2 q1 = ((const ulonglong2*)vp)[1];
        ulonglong2 q2 = ((const ulonglong2*)vp)[2];
        ulonglong2 q3 = ((const ulonglong2*)vp)[3];
        ulonglong2 q4 = ((const ulonglong2*)vp)[4];
        unsigned long long q5 = *(const unsigned long long*)(vp + 20);

        #pragma unroll 4
        for (int jj = 0; jj < 64; jj++) {
            const float* np = vp + VGS;     // g_vg padded: overrun safe
            ulonglong2 n0 = ((const ulonglong2*)np)[0];
            ulonglong2 n1 = ((const ulonglong2*)np)[1];
            ulonglong2 n2 = ((const ulonglong2*)np)[2];
            ulonglong2 n3 = ((const ulonglong2*)np)[3];
            ulonglong2 n4 = ((const ulonglong2*)np)[4];
            unsigned long long n5 = *(const unsigned long long*)(np + 20);

            unsigned long long s0 = f2mul(q0.x, A0.x);
            unsigned long long s1 = f2mul(q0.y, A0.y);
            s0 = f2fma(q1.x, A1.x, s0); s1 = f2fma(q1.y, A1.y, s1);
            s0 = f2fma(q2.x, A2.x, s0); s1 = f2fma(q2.y, A2.y, s1);
            s0 = f2fma(q3.x, A3.x, s0); s1 = f2fma(q3.y, A3.y, s1);
            s0 = f2fma(q4.x, A4.x, s0); s1 = f2fma(q4.y, A4.y, s1);
            s0 = f2fma(q5, A5, s0);
            s0 = f2add(s0, s1);
            float lo = __uint_as_float((unsigned)(s0 & 0xffffffffull));
            float hi = __uint_as_float((unsigned)(s0 >> 32));
            drow[jj] = fmaxf(-2.0f * (lo + hi), 1e-12f);

            q0 = n0; q1 = n1; q2 = n2; q3 = n3; q4 = n4; q5 = n5;
            vp = np;
        }
    }
    __syncthreads();

    // ---------------- phase 2: per-token selection (warp = token, 2 reps) ----------------
    #pragma unroll 1
    for (int rep = 0; rep < 2; rep++) {
        int t = warp + rep * 8;
        const float* row = d2mat + t * D2STR;

        // pass A: lane-min over my 32 strided values
        float mv = 3.4e38f;
        #pragma unroll
        for (int i = 0; i < 32; i++) mv = fminf(mv, row[i * 32 + lane]);

        // tau = 10th smallest of the 32 lane-mins (safe threshold: >= true 10th)
        float cur = mv, tau = 3.4e38f;
        #pragma unroll
        for (int r = 0; r < TOPK; r++) {
            float m = cur;
            #pragma unroll
            for (int off = 16; off; off >>= 1)
                m = fminf(m, __shfl_xor_sync(0xffffffffu, m, off));
            tau = m;
            if (cur == m) cur = 3.4e38f;
        }

        // pass B: append survivors (<= tau); skip lanes whose min is > tau
        if (mv <= tau) {
            #pragma unroll 4
            for (int i = 0; i < 32; i++) {
                float v = row[i * 32 + lane];
                if (v <= tau) {
                    int p = atomicAdd(&lcnt[t], 1);
                    if (p < SCAP) { lv[t * SCAP + p] = v; lj[t * SCAP + p] = i * 32 + lane; }
                }
            }
        }
        __syncwarp();

        // exact top-10 over survivors, u64 keys (d2, j) => deterministic
        int n = min(lcnt[t], SCAP);
        unsigned long long k0 = 0xFFFFFFFFFFFFFFFFull, k1 = 0xFFFFFFFFFFFFFFFFull;
        if (lane < n)
            k0 = ((unsigned long long)__float_as_uint(lv[t * SCAP + lane]) << 32)
               | (unsigned)lj[t * SCAP + lane];
        if (lane + 32 < n)
            k1 = ((unsigned long long)__float_as_uint(lv[t * SCAP + lane + 32]) << 32)
               | (unsigned)lj[t * SCAP + lane + 32];

        unsigned long long mywin = 0;
        #pragma unroll
        for (int r = 0; r < TOPK; r++) {
            unsigned long long c = (k0 < k1) ? k0 : k1;
            unsigned long long wm = c;
            #pragma unroll
            for (int off = 16; off; off >>= 1) {
                unsigned long long o = __shfl_xor_sync(0xffffffffu, wm, off);
                wm = (o < wm) ? o : wm;
            }
            if (k0 == wm) k0 = 0xFFFFFFFFFFFFFFFFull;
            else if (k1 == wm) k1 = 0xFFFFFFFFFFFFFFFFull;
            if (lane == r) mywin = wm;
        }

        // weights + ids: lanes 0..9 winners, lane 10 self
        float e = 0.0f; int ci = 0;
        if (lane < TOPK) {
            float d2 = __uint_as_float((unsigned)(mywin >> 32));
            int j = (int)(mywin & 0xffffffffu);
            float sc = expf(-RHO_C * sqrtf(d2));
            e = expf(sc - 1.0f);
            ci = cand[cid * CANDN + j];
        } else if (lane == TOPK) {
            e = 1.0f;
            ci = x[tok_s[t]];
        }
        float ep = e;
        #pragma unroll
        for (int off = 16; off; off >>= 1) ep += __shfl_xor_sync(0xffffffffu, ep, off);
        float inv = 1.0f / ep;
        if (lane <= TOPK) { sw_s[t * 12 + lane] = e * inv; si_s[t * 12 + lane] = ci; }
    }
    __syncthreads();

    // ---------------- epilogue: weighted embedding gather (warp per token, 2 reps) ----------------
    #pragma unroll 1
    for (int rep = 0; rep < 2; rep++) {
        int t = warp + rep * 8;
        if (t < nIn) {
            int token2 = tok_s[t];
            float4 a0 = make_float4(0.f, 0.f, 0.f, 0.f);
            #pragma unroll
            for (int kk = 0; kk < 11; kk++) {
                float w = sw_s[t * 12 + kk];
                float4 e0 = ((const float4*)(Eemb + (size_t)si_s[t * 12 + kk] * HD))[lane];
                a0.x += w * e0.x; a0.y += w * e0.y; a0.z += w * e0.z; a0.w += w * e0.w;
            }
            ((float4*)(out + (size_t)token2 * HD))[lane] = a0;
        }
    }
}

// ============ launch ============
extern "C" void kernel_launch(void* const* d_in, const int* in_sizes, int n_in,
                              void* d_out, int out_size) {
    const int*   x     = (const int*)  d_in[0];
    const int*   tslot = (const int*)  d_in[1];
    const float* vecs  = (const float*)d_in[2];
    const float* Eemb  = (const float*)d_in[3];
    const int*   Iarr  = (const int*)  d_in[4];
    const int*   cand  = (const int*)  d_in[5];
    const float* te    = (const float*)d_in[6];
    const float* Wseq1 = (const float*)d_in[7];
    const float* bseq1 = (const float*)d_in[8];
    const float* Wseq2 = (const float*)d_in[9];
    const float* bseq2 = (const float*)d_in[10];
    const float* Wto1  = (const float*)d_in[11];
    const float* bto1  = (const float*)d_in[12];
    const float* Wto2  = (const float*)d_in[13];
    const float* bto2  = (const float*)d_in[14];
    const float* Wti1  = (const float*)d_in[15];
    const float* bti1  = (const float*)d_in[16];
    const float* Wti2  = (const float*)d_in[17];
    const float* bti2  = (const float*)d_in[18];
    float* out = (float*)d_out;

    cudaFuncSetAttribute(k3_score, cudaFuncAttributeMaxDynamicSharedMemorySize, K3_SMEM);

    k_mid<<<337, 128>>>(x, tslot, vecs, cand, Iarr, te,
                        Wseq1, bseq1, Wseq2, bseq2,
                        Wto1, bto1, Wto2, bto2,
                        Wti1, bti1, Wti2, bti2);
    k3_score<<<NWORK_MAX, 256, K3_SMEM>>>(x, cand, Eemb, out);
}